// round 1
// baseline (speedup 1.0000x reference)
#include <cuda_runtime.h>
#include <cuda_bf16.h>
#include <cstdint>

// ---------------- problem constants ----------------
#define NTOK   16384          // B*T = 8*2048
#define DDIM   512
#define HDIM   1408
#define NEXP   8
#define KTOP   2
#define NPAIR  (NTOK*KTOP)    // 32768
#define MAX_MT 520            // max 64-row M tiles across experts

// ---------------- device scratch (no allocations allowed) ----------------
__device__ float g_h[(size_t)NPAIR * HDIM];   // 184 MB intermediate h
__device__ float g_y[(size_t)NPAIR * DDIM];   // 67 MB per-pair expert output
__device__ int   g_tok_of_pair[NPAIR];
__device__ int   g_slot[NTOK * KTOP];         // (tok,k) -> grouped pair slot
__device__ int   g_exp_of_tok[NTOK * KTOP];
__device__ float g_wt_of_tok[NTOK * KTOP];
__device__ int   g_counts[NEXP];
__device__ int   g_cursor[NEXP];
__device__ int   g_offsets[NEXP + 1];
__device__ float g_usage[NEXP];
__device__ int   g_tile_expert[MAX_MT];
__device__ int   g_tile_row[MAX_MT];
__device__ int   g_ntiles;

// ---------------- init ----------------
__global__ void init_kernel() {
    int i = threadIdx.x;
    if (i < NEXP) { g_counts[i] = 0; g_cursor[i] = 0; g_usage[i] = 0.f; }
}

// ---------------- router: warp per token ----------------
__global__ void __launch_bounds__(256) router_kernel(const float* __restrict__ x,
                                                     const float* __restrict__ rw) {
    int warp = threadIdx.x >> 5, lane = threadIdx.x & 31;
    int tok = blockIdx.x * 8 + warp;
    if (tok >= NTOK) return;
    const float* xr = x + (size_t)tok * DDIM;

    float xv[16];
#pragma unroll
    for (int i = 0; i < 16; i++) xv[i] = xr[lane + 32 * i];

    float logits[NEXP];
#pragma unroll
    for (int e = 0; e < NEXP; e++) {
        const float* wr = rw + e * DDIM;
        float s = 0.f;
#pragma unroll
        for (int i = 0; i < 16; i++) s += xv[i] * wr[lane + 32 * i];
#pragma unroll
        for (int o = 16; o > 0; o >>= 1) s += __shfl_xor_sync(0xffffffffu, s, o);
        logits[e] = s;
    }
    if (lane == 0) {
        float m = logits[0];
#pragma unroll
        for (int e = 1; e < NEXP; e++) m = fmaxf(m, logits[e]);
        float p[NEXP], Z = 0.f;
#pragma unroll
        for (int e = 0; e < NEXP; e++) { p[e] = __expf(logits[e] - m); Z += p[e]; }
        float inv = 1.f / Z;
        // top-2 (first-index wins ties, matching lax.top_k)
        int a = 0;
#pragma unroll
        for (int e = 1; e < NEXP; e++) if (p[e] > p[a]) a = e;
        int b = (a == 0) ? 1 : 0;
#pragma unroll
        for (int e = 0; e < NEXP; e++) { if (e == a) continue; if (p[e] > p[b]) b = e; }
        float pa = p[a] * inv, pb = p[b] * inv;
        float wsum = pa + pb;
        g_exp_of_tok[tok * 2 + 0] = a;
        g_exp_of_tok[tok * 2 + 1] = b;
        g_wt_of_tok[tok * 2 + 0] = pa / wsum;
        g_wt_of_tok[tok * 2 + 1] = pb / wsum;
        atomicAdd(&g_counts[a], 1);
        atomicAdd(&g_counts[b], 1);
#pragma unroll
        for (int e = 0; e < NEXP; e++) atomicAdd(&g_usage[e], p[e] * inv);
    }
}

// ---------------- scan + tile descriptor list ----------------
__global__ void scan_kernel() {
    if (threadIdx.x != 0) return;
    int off = 0;
    for (int e = 0; e < NEXP; e++) { g_offsets[e] = off; off += g_counts[e]; }
    g_offsets[NEXP] = off;
    int nt = 0;
    for (int e = 0; e < NEXP; e++) {
        int cnt = g_counts[e];
        for (int r = 0; r < cnt; r += 64) {
            g_tile_expert[nt] = e;
            g_tile_row[nt] = g_offsets[e] + r;
            nt++;
        }
    }
    g_ntiles = nt;
}

// ---------------- build grouped pair arrays ----------------
__global__ void build_kernel() {
    int i = blockIdx.x * blockDim.x + threadIdx.x;
    if (i >= NTOK * KTOP) return;
    int e = g_exp_of_tok[i];
    int pos = g_offsets[e] + atomicAdd(&g_cursor[e], 1);
    g_tok_of_pair[pos] = i >> 1;
    g_slot[i] = pos;
}

// ---------------- GEMM1: h = silu(x@w1^T) * (x@w3^T), grouped rows ----------------
// 64x64 tile, BK=16, 256 threads, 4x4 per-thread microtile, dual accumulators.
__global__ void __launch_bounds__(256) gemm1_kernel(const float* __restrict__ x,
                                                    const float* __restrict__ w1,
                                                    const float* __restrict__ w3) {
    int mt = blockIdx.y;
    if (mt >= g_ntiles) return;
    int e = g_tile_expert[mt];
    int row0 = g_tile_row[mt];
    int valid = g_offsets[e + 1] - row0; if (valid > 64) valid = 64;
    int n0 = blockIdx.x * 64;

    const float* W1 = w1 + (size_t)e * HDIM * DDIM + (size_t)n0 * DDIM;
    const float* W3 = w3 + (size_t)e * HDIM * DDIM + (size_t)n0 * DDIM;

    __shared__ float As[16][64];
    __shared__ float B1s[16][64];
    __shared__ float B3s[16][64];

    int tid = threadIdx.x;
    int tm = tid >> 4, tn = tid & 15;
    float acc1[4][4] = {}, acc3[4][4] = {};

    int lrow = tid >> 2, lk = (tid & 3) * 4;
    const float* arow = nullptr;
    if (lrow < valid) arow = x + (size_t)g_tok_of_pair[row0 + lrow] * DDIM;
    const float* b1row = W1 + (size_t)lrow * DDIM;
    const float* b3row = W3 + (size_t)lrow * DDIM;

    for (int k0 = 0; k0 < DDIM; k0 += 16) {
        float4 av = make_float4(0.f, 0.f, 0.f, 0.f);
        if (arow) av = *(const float4*)(arow + k0 + lk);
        float4 b1v = *(const float4*)(b1row + k0 + lk);
        float4 b3v = *(const float4*)(b3row + k0 + lk);
        __syncthreads();
        As[lk + 0][lrow] = av.x;  As[lk + 1][lrow] = av.y;
        As[lk + 2][lrow] = av.z;  As[lk + 3][lrow] = av.w;
        B1s[lk + 0][lrow] = b1v.x; B1s[lk + 1][lrow] = b1v.y;
        B1s[lk + 2][lrow] = b1v.z; B1s[lk + 3][lrow] = b1v.w;
        B3s[lk + 0][lrow] = b3v.x; B3s[lk + 1][lrow] = b3v.y;
        B3s[lk + 2][lrow] = b3v.z; B3s[lk + 3][lrow] = b3v.w;
        __syncthreads();
#pragma unroll
        for (int k = 0; k < 16; k++) {
            float4 a  = *(const float4*)&As[k][tm * 4];
            float4 b1 = *(const float4*)&B1s[k][tn * 4];
            float4 b3 = *(const float4*)&B3s[k][tn * 4];
            float aa[4] = {a.x, a.y, a.z, a.w};
            float bb1[4] = {b1.x, b1.y, b1.z, b1.w};
            float bb3[4] = {b3.x, b3.y, b3.z, b3.w};
#pragma unroll
            for (int i = 0; i < 4; i++)
#pragma unroll
                for (int j = 0; j < 4; j++) {
                    acc1[i][j] += aa[i] * bb1[j];
                    acc3[i][j] += aa[i] * bb3[j];
                }
        }
    }
#pragma unroll
    for (int i = 0; i < 4; i++) {
        int r = tm * 4 + i;
        if (r < valid) {
            float* hr = g_h + (size_t)(row0 + r) * HDIM + n0 + tn * 4;
#pragma unroll
            for (int j = 0; j < 4; j++) {
                float z = acc1[i][j];
                float s = z / (1.f + __expf(-z));
                hr[j] = s * acc3[i][j];
            }
        }
    }
}

// ---------------- GEMM2: y = h @ w2^T ----------------
__global__ void __launch_bounds__(256) gemm2_kernel(const float* __restrict__ w2) {
    int mt = blockIdx.y;
    if (mt >= g_ntiles) return;
    int e = g_tile_expert[mt];
    int row0 = g_tile_row[mt];
    int valid = g_offsets[e + 1] - row0; if (valid > 64) valid = 64;
    int n0 = blockIdx.x * 64;

    const float* W2 = w2 + (size_t)e * DDIM * HDIM + (size_t)n0 * HDIM;

    __shared__ float As[16][64];
    __shared__ float Bs[16][64];

    int tid = threadIdx.x;
    int tm = tid >> 4, tn = tid & 15;
    float acc[4][4] = {};

    int lrow = tid >> 2, lk = (tid & 3) * 4;
    const float* arow = (lrow < valid) ? (g_h + (size_t)(row0 + lrow) * HDIM) : nullptr;
    const float* brow = W2 + (size_t)lrow * HDIM;

    for (int k0 = 0; k0 < HDIM; k0 += 16) {
        float4 av = make_float4(0.f, 0.f, 0.f, 0.f);
        if (arow) av = *(const float4*)(arow + k0 + lk);
        float4 bv = *(const float4*)(brow + k0 + lk);
        __syncthreads();
        As[lk + 0][lrow] = av.x; As[lk + 1][lrow] = av.y;
        As[lk + 2][lrow] = av.z; As[lk + 3][lrow] = av.w;
        Bs[lk + 0][lrow] = bv.x; Bs[lk + 1][lrow] = bv.y;
        Bs[lk + 2][lrow] = bv.z; Bs[lk + 3][lrow] = bv.w;
        __syncthreads();
#pragma unroll
        for (int k = 0; k < 16; k++) {
            float4 a = *(const float4*)&As[k][tm * 4];
            float4 b = *(const float4*)&Bs[k][tn * 4];
            float aa[4] = {a.x, a.y, a.z, a.w};
            float bb[4] = {b.x, b.y, b.z, b.w};
#pragma unroll
            for (int i = 0; i < 4; i++)
#pragma unroll
                for (int j = 0; j < 4; j++)
                    acc[i][j] += aa[i] * bb[j];
        }
    }
#pragma unroll
    for (int i = 0; i < 4; i++) {
        int r = tm * 4 + i;
        if (r < valid) {
            float* yr = g_y + (size_t)(row0 + r) * DDIM + n0 + tn * 4;
#pragma unroll
            for (int j = 0; j < 4; j++) yr[j] = acc[i][j];
        }
    }
}

// ---------------- combine: out[tok] = w0*y[slot0] + w1*y[slot1] ----------------
__global__ void combine_kernel(float* __restrict__ out) {
    int i = blockIdx.x * blockDim.x + threadIdx.x;
    const int D4 = DDIM / 4;
    if (i >= NTOK * D4) return;
    int tok = i / D4;
    int d4 = i - tok * D4;
    int s0 = g_slot[tok * 2 + 0], s1 = g_slot[tok * 2 + 1];
    float w0 = g_wt_of_tok[tok * 2 + 0], w1 = g_wt_of_tok[tok * 2 + 1];
    const float4* y4 = (const float4*)g_y;
    float4 a = y4[(size_t)s0 * D4 + d4];
    float4 b = y4[(size_t)s1 * D4 + d4];
    float4 r;
    r.x = w0 * a.x + w1 * b.x;
    r.y = w0 * a.y + w1 * b.y;
    r.z = w0 * a.z + w1 * b.z;
    r.w = w0 * a.w + w1 * b.w;
    ((float4*)out)[i] = r;
}

// ---------------- aux loss ----------------
__global__ void finalize_kernel(float* __restrict__ out, int out_size) {
    if (threadIdx.x != 0 || blockIdx.x != 0) return;
    if (out_size > NTOK * DDIM) {
        float s = 0.f;
        for (int e = 0; e < NEXP; e++) {
            float u = g_usage[e] / (float)NTOK;
            s += u * u;
        }
        out[NTOK * DDIM] = (float)NEXP * 0.01f * s;
    }
}

// ---------------- launch ----------------
extern "C" void kernel_launch(void* const* d_in, const int* in_sizes, int n_in,
                              void* d_out, int out_size) {
    const float* x  = (const float*)d_in[0];
    const float* rw = (const float*)d_in[1];
    const float* w1 = (const float*)d_in[2];
    const float* w2 = (const float*)d_in[3];
    const float* w3 = (const float*)d_in[4];
    float* out = (float*)d_out;

    init_kernel<<<1, 32>>>();
    router_kernel<<<NTOK / 8, 256>>>(x, rw);
    scan_kernel<<<1, 32>>>();
    build_kernel<<<(NTOK * KTOP + 255) / 256, 256>>>();
    gemm1_kernel<<<dim3(HDIM / 64, MAX_MT), 256>>>(x, w1, w3);
    gemm2_kernel<<<dim3(DDIM / 64, MAX_MT), 256>>>(w2);
    combine_kernel<<<(NTOK * (DDIM / 4) + 255) / 256, 256>>>(out);
    finalize_kernel<<<1, 32>>>(out, out_size);
}

// round 3
// speedup vs baseline: 2.3784x; 2.3784x over previous
#include <cuda_runtime.h>
#include <cuda_bf16.h>
#include <cstdint>

// ---------------- problem constants ----------------
#define NTOK   16384          // B*T = 8*2048
#define DDIM   512
#define HDIM   1408
#define NEXP   8
#define KTOP   2
#define NPAIR  (NTOK*KTOP)    // 32768
#define MAX_MT 520            // max 64-row M tiles across experts

// ---------------- device scratch (no allocations allowed) ----------------
__device__ float g_h[(size_t)NPAIR * HDIM];   // 184 MB intermediate h
__device__ float g_y[(size_t)NPAIR * DDIM];   // 67 MB per-pair expert output
__device__ int   g_tok_of_pair[NPAIR];
__device__ int   g_slot[NTOK * KTOP];
__device__ int   g_exp_of_tok[NTOK * KTOP];
__device__ float g_wt_of_tok[NTOK * KTOP];
__device__ int   g_counts[NEXP];
__device__ int   g_cursor[NEXP];
__device__ int   g_offsets[NEXP + 1];
__device__ float g_usage[NEXP];
__device__ int   g_tile_expert[MAX_MT];
__device__ int   g_tile_row[MAX_MT];
__device__ int   g_ntiles;

// ---------------- tf32 helpers ----------------
__device__ __forceinline__ uint32_t f2tf32(float f) {
    uint32_t u;
    asm("cvt.rna.tf32.f32 %0, %1;" : "=r"(u) : "f"(f));
    return u;
}

__device__ __forceinline__ void mma_tf32(float* c, const uint32_t* a, const uint32_t* b) {
    asm volatile(
        "mma.sync.aligned.m16n8k8.row.col.f32.tf32.tf32.f32 "
        "{%0,%1,%2,%3}, {%4,%5,%6,%7}, {%8,%9}, {%0,%1,%2,%3};\n"
        : "+f"(c[0]), "+f"(c[1]), "+f"(c[2]), "+f"(c[3])
        : "r"(a[0]), "r"(a[1]), "r"(a[2]), "r"(a[3]), "r"(b[0]), "r"(b[1]));
}

// ---------------- init ----------------
__global__ void init_kernel() {
    int i = threadIdx.x;
    if (i < NEXP) { g_counts[i] = 0; g_cursor[i] = 0; g_usage[i] = 0.f; }
}

// ---------------- router: warp per token ----------------
__global__ void __launch_bounds__(256) router_kernel(const float* __restrict__ x,
                                                     const float* __restrict__ rw) {
    int warp = threadIdx.x >> 5, lane = threadIdx.x & 31;
    int tok = blockIdx.x * 8 + warp;
    if (tok >= NTOK) return;
    const float* xr = x + (size_t)tok * DDIM;

    float xv[16];
#pragma unroll
    for (int i = 0; i < 16; i++) xv[i] = xr[lane + 32 * i];

    float logits[NEXP];
#pragma unroll
    for (int e = 0; e < NEXP; e++) {
        const float* wr = rw + e * DDIM;
        float s = 0.f;
#pragma unroll
        for (int i = 0; i < 16; i++) s += xv[i] * wr[lane + 32 * i];
#pragma unroll
        for (int o = 16; o > 0; o >>= 1) s += __shfl_xor_sync(0xffffffffu, s, o);
        logits[e] = s;
    }
    if (lane == 0) {
        float m = logits[0];
#pragma unroll
        for (int e = 1; e < NEXP; e++) m = fmaxf(m, logits[e]);
        float p[NEXP], Z = 0.f;
#pragma unroll
        for (int e = 0; e < NEXP; e++) { p[e] = __expf(logits[e] - m); Z += p[e]; }
        float inv = 1.f / Z;
        int a = 0;
#pragma unroll
        for (int e = 1; e < NEXP; e++) if (p[e] > p[a]) a = e;
        int b = (a == 0) ? 1 : 0;
#pragma unroll
        for (int e = 0; e < NEXP; e++) { if (e == a) continue; if (p[e] > p[b]) b = e; }
        float pa = p[a] * inv, pb = p[b] * inv;
        float wsum = pa + pb;
        g_exp_of_tok[tok * 2 + 0] = a;
        g_exp_of_tok[tok * 2 + 1] = b;
        g_wt_of_tok[tok * 2 + 0] = pa / wsum;
        g_wt_of_tok[tok * 2 + 1] = pb / wsum;
        atomicAdd(&g_counts[a], 1);
        atomicAdd(&g_counts[b], 1);
#pragma unroll
        for (int e = 0; e < NEXP; e++) atomicAdd(&g_usage[e], p[e] * inv);
    }
}

// ---------------- scan + tile descriptor list ----------------
__global__ void scan_kernel() {
    if (threadIdx.x != 0) return;
    int off = 0;
    for (int e = 0; e < NEXP; e++) { g_offsets[e] = off; off += g_counts[e]; }
    g_offsets[NEXP] = off;
    int nt = 0;
    for (int e = 0; e < NEXP; e++) {
        int cnt = g_counts[e];
        for (int r = 0; r < cnt; r += 64) {
            g_tile_expert[nt] = e;
            g_tile_row[nt] = g_offsets[e] + r;
            nt++;
        }
    }
    g_ntiles = nt;
}

// ---------------- build grouped pair arrays ----------------
__global__ void build_kernel() {
    int i = blockIdx.x * blockDim.x + threadIdx.x;
    if (i >= NTOK * KTOP) return;
    int e = g_exp_of_tok[i];
    int pos = g_offsets[e] + atomicAdd(&g_cursor[e], 1);
    g_tok_of_pair[pos] = i >> 1;
    g_slot[i] = pos;
}

// ============================================================
// GEMM1 (tf32 tensor cores): h = silu(x@w1^T) * (x@w3^T)
// CTA tile 64(M pairs) x 64(N h-cols), BK=32, 8 warps (32x16 each).
// ============================================================
#define SSTRIDE 36   // smem row stride (floats) -> conflict-free fragment LDS

__global__ void __launch_bounds__(256) gemm1_kernel(const float* __restrict__ x,
                                                    const float* __restrict__ w1,
                                                    const float* __restrict__ w3) {
    int mt = blockIdx.y;
    if (mt >= g_ntiles) return;
    int e = g_tile_expert[mt];
    int row0 = g_tile_row[mt];
    int valid = g_offsets[e + 1] - row0; if (valid > 64) valid = 64;
    int n0 = blockIdx.x * 64;

    const float* W1 = w1 + (size_t)e * HDIM * DDIM + (size_t)n0 * DDIM;
    const float* W3 = w3 + (size_t)e * HDIM * DDIM + (size_t)n0 * DDIM;

    __shared__ uint32_t As[64 * SSTRIDE];
    __shared__ uint32_t B1s[64 * SSTRIDE];
    __shared__ uint32_t B3s[64 * SSTRIDE];

    int tid = threadIdx.x;
    int lane = tid & 31, w = tid >> 5;
    int wm = (w & 1) * 32, wn = (w >> 1) * 16;
    int gid = lane >> 2, tig = lane & 3;

    // loader mapping: row = tid>>2 (0..63), cols [lc, lc+8)
    int lr = tid >> 2;
    int lc = (tid & 3) * 8;
    const float* arow = nullptr;
    if (lr < valid) arow = x + (size_t)g_tok_of_pair[row0 + lr] * DDIM;
    const float* b1row = W1 + (size_t)lr * DDIM;
    const float* b3row = W3 + (size_t)lr * DDIM;

    float acc1[2][2][4] = {}, acc3[2][2][4] = {};

    float4 ra[2], rb1[2], rb3[2];
    // prefetch chunk 0
    {
        ra[0] = ra[1] = make_float4(0.f, 0.f, 0.f, 0.f);
        if (arow) { ra[0] = *(const float4*)(arow + lc); ra[1] = *(const float4*)(arow + lc + 4); }
        rb1[0] = *(const float4*)(b1row + lc); rb1[1] = *(const float4*)(b1row + lc + 4);
        rb3[0] = *(const float4*)(b3row + lc); rb3[1] = *(const float4*)(b3row + lc + 4);
    }

    const int NC = DDIM / 32;   // 16 chunks
    for (int kc = 0; kc < NC; kc++) {
        __syncthreads();
        // store prefetched chunk with tf32 rounding
        uint32_t* Ar = As + lr * SSTRIDE + lc;
        uint32_t* B1r = B1s + lr * SSTRIDE + lc;
        uint32_t* B3r = B3s + lr * SSTRIDE + lc;
        Ar[0] = f2tf32(ra[0].x); Ar[1] = f2tf32(ra[0].y); Ar[2] = f2tf32(ra[0].z); Ar[3] = f2tf32(ra[0].w);
        Ar[4] = f2tf32(ra[1].x); Ar[5] = f2tf32(ra[1].y); Ar[6] = f2tf32(ra[1].z); Ar[7] = f2tf32(ra[1].w);
        B1r[0] = f2tf32(rb1[0].x); B1r[1] = f2tf32(rb1[0].y); B1r[2] = f2tf32(rb1[0].z); B1r[3] = f2tf32(rb1[0].w);
        B1r[4] = f2tf32(rb1[1].x); B1r[5] = f2tf32(rb1[1].y); B1r[6] = f2tf32(rb1[1].z); B1r[7] = f2tf32(rb1[1].w);
        B3r[0] = f2tf32(rb3[0].x); B3r[1] = f2tf32(rb3[0].y); B3r[2] = f2tf32(rb3[0].z); B3r[3] = f2tf32(rb3[0].w);
        B3r[4] = f2tf32(rb3[1].x); B3r[5] = f2tf32(rb3[1].y); B3r[6] = f2tf32(rb3[1].z); B3r[7] = f2tf32(rb3[1].w);
        __syncthreads();

        // prefetch next chunk (overlaps with mma below)
        if (kc + 1 < NC) {
            int k0 = (kc + 1) * 32;
            ra[0] = ra[1] = make_float4(0.f, 0.f, 0.f, 0.f);
            if (arow) { ra[0] = *(const float4*)(arow + k0 + lc); ra[1] = *(const float4*)(arow + k0 + lc + 4); }
            rb1[0] = *(const float4*)(b1row + k0 + lc); rb1[1] = *(const float4*)(b1row + k0 + lc + 4);
            rb3[0] = *(const float4*)(b3row + k0 + lc); rb3[1] = *(const float4*)(b3row + k0 + lc + 4);
        }

#pragma unroll
        for (int kk = 0; kk < 4; kk++) {
            int k = kk * 8;
            uint32_t afr[2][4];
#pragma unroll
            for (int m = 0; m < 2; m++) {
                int r = wm + m * 16 + gid;
                afr[m][0] = As[r * SSTRIDE + k + tig];
                afr[m][1] = As[(r + 8) * SSTRIDE + k + tig];
                afr[m][2] = As[r * SSTRIDE + k + tig + 4];
                afr[m][3] = As[(r + 8) * SSTRIDE + k + tig + 4];
            }
#pragma unroll
            for (int n = 0; n < 2; n++) {
                int c = wn + n * 8 + gid;
                uint32_t b1f[2] = { B1s[c * SSTRIDE + k + tig], B1s[c * SSTRIDE + k + tig + 4] };
                uint32_t b3f[2] = { B3s[c * SSTRIDE + k + tig], B3s[c * SSTRIDE + k + tig + 4] };
#pragma unroll
                for (int m = 0; m < 2; m++) {
                    mma_tf32(acc1[m][n], afr[m], b1f);
                    mma_tf32(acc3[m][n], afr[m], b3f);
                }
            }
        }
    }

    // epilogue: h = silu(acc1) * acc3
#pragma unroll
    for (int m = 0; m < 2; m++) {
#pragma unroll
        for (int n = 0; n < 2; n++) {
            int col = n0 + wn + n * 8 + 2 * tig;
#pragma unroll
            for (int half = 0; half < 2; half++) {
                int r = wm + m * 16 + gid + half * 8;
                if (r < valid) {
                    float* hr = g_h + (size_t)(row0 + r) * HDIM + col;
                    float z0 = acc1[m][n][half * 2 + 0];
                    float z1 = acc1[m][n][half * 2 + 1];
                    float s0 = z0 / (1.f + __expf(-z0));
                    float s1 = z1 / (1.f + __expf(-z1));
                    hr[0] = s0 * acc3[m][n][half * 2 + 0];
                    hr[1] = s1 * acc3[m][n][half * 2 + 1];
                }
            }
        }
    }
}

// ============================================================
// GEMM2 (tf32 tensor cores): y = h @ w2^T
// CTA tile 64 x 64, BK=32, K=1408 (44 chunks)
// ============================================================
__global__ void __launch_bounds__(256) gemm2_kernel(const float* __restrict__ w2) {
    int mt = blockIdx.y;
    if (mt >= g_ntiles) return;
    int e = g_tile_expert[mt];
    int row0 = g_tile_row[mt];
    int valid = g_offsets[e + 1] - row0; if (valid > 64) valid = 64;
    int n0 = blockIdx.x * 64;

    const float* W2 = w2 + (size_t)e * DDIM * HDIM + (size_t)n0 * HDIM;

    __shared__ uint32_t As[64 * SSTRIDE];
    __shared__ uint32_t Bs[64 * SSTRIDE];

    int tid = threadIdx.x;
    int lane = tid & 31, w = tid >> 5;
    int wm = (w & 1) * 32, wn = (w >> 1) * 16;
    int gid = lane >> 2, tig = lane & 3;

    int lr = tid >> 2;
    int lc = (tid & 3) * 8;
    const float* arow = (lr < valid) ? (g_h + (size_t)(row0 + lr) * HDIM) : nullptr;
    const float* brow = W2 + (size_t)lr * HDIM;

    float acc[2][2][4] = {};

    float4 ra[2], rb[2];
    {
        ra[0] = ra[1] = make_float4(0.f, 0.f, 0.f, 0.f);
        if (arow) { ra[0] = *(const float4*)(arow + lc); ra[1] = *(const float4*)(arow + lc + 4); }
        rb[0] = *(const float4*)(brow + lc); rb[1] = *(const float4*)(brow + lc + 4);
    }

    const int NC = HDIM / 32;   // 44 chunks
    for (int kc = 0; kc < NC; kc++) {
        __syncthreads();
        uint32_t* Ar = As + lr * SSTRIDE + lc;
        uint32_t* Br = Bs + lr * SSTRIDE + lc;
        Ar[0] = f2tf32(ra[0].x); Ar[1] = f2tf32(ra[0].y); Ar[2] = f2tf32(ra[0].z); Ar[3] = f2tf32(ra[0].w);
        Ar[4] = f2tf32(ra[1].x); Ar[5] = f2tf32(ra[1].y); Ar[6] = f2tf32(ra[1].z); Ar[7] = f2tf32(ra[1].w);
        Br[0] = f2tf32(rb[0].x); Br[1] = f2tf32(rb[0].y); Br[2] = f2tf32(rb[0].z); Br[3] = f2tf32(rb[0].w);
        Br[4] = f2tf32(rb[1].x); Br[5] = f2tf32(rb[1].y); Br[6] = f2tf32(rb[1].z); Br[7] = f2tf32(rb[1].w);
        __syncthreads();

        if (kc + 1 < NC) {
            int k0 = (kc + 1) * 32;
            ra[0] = ra[1] = make_float4(0.f, 0.f, 0.f, 0.f);
            if (arow) { ra[0] = *(const float4*)(arow + k0 + lc); ra[1] = *(const float4*)(arow + k0 + lc + 4); }
            rb[0] = *(const float4*)(brow + k0 + lc); rb[1] = *(const float4*)(brow + k0 + lc + 4);
        }

#pragma unroll
        for (int kk = 0; kk < 4; kk++) {
            int k = kk * 8;
            uint32_t afr[2][4];
#pragma unroll
            for (int m = 0; m < 2; m++) {
                int r = wm + m * 16 + gid;
                afr[m][0] = As[r * SSTRIDE + k + tig];
                afr[m][1] = As[(r + 8) * SSTRIDE + k + tig];
                afr[m][2] = As[r * SSTRIDE + k + tig + 4];
                afr[m][3] = As[(r + 8) * SSTRIDE + k + tig + 4];
            }
#pragma unroll
            for (int n = 0; n < 2; n++) {
                int c = wn + n * 8 + gid;
                uint32_t bf[2] = { Bs[c * SSTRIDE + k + tig], Bs[c * SSTRIDE + k + tig + 4] };
#pragma unroll
                for (int m = 0; m < 2; m++) {
                    mma_tf32(acc[m][n], afr[m], bf);
                }
            }
        }
    }

#pragma unroll
    for (int m = 0; m < 2; m++) {
#pragma unroll
        for (int n = 0; n < 2; n++) {
            int col = n0 + wn + n * 8 + 2 * tig;
#pragma unroll
            for (int half = 0; half < 2; half++) {
                int r = wm + m * 16 + gid + half * 8;
                if (r < valid) {
                    float* yr = g_y + (size_t)(row0 + r) * DDIM + col;
                    yr[0] = acc[m][n][half * 2 + 0];
                    yr[1] = acc[m][n][half * 2 + 1];
                }
            }
        }
    }
}

// ---------------- combine: out[tok] = w0*y[slot0] + w1*y[slot1] ----------------
__global__ void combine_kernel(float* __restrict__ out) {
    int i = blockIdx.x * blockDim.x + threadIdx.x;
    const int D4 = DDIM / 4;
    if (i >= NTOK * D4) return;
    int tok = i / D4;
    int d4 = i - tok * D4;
    int s0 = g_slot[tok * 2 + 0], s1 = g_slot[tok * 2 + 1];
    float w0 = g_wt_of_tok[tok * 2 + 0], w1 = g_wt_of_tok[tok * 2 + 1];
    const float4* y4 = (const float4*)g_y;
    float4 a = y4[(size_t)s0 * D4 + d4];
    float4 b = y4[(size_t)s1 * D4 + d4];
    float4 r;
    r.x = w0 * a.x + w1 * b.x;
    r.y = w0 * a.y + w1 * b.y;
    r.z = w0 * a.z + w1 * b.z;
    r.w = w0 * a.w + w1 * b.w;
    ((float4*)out)[i] = r;
}

// ---------------- aux loss ----------------
__global__ void finalize_kernel(float* __restrict__ out, int out_size) {
    if (threadIdx.x != 0 || blockIdx.x != 0) return;
    if (out_size > NTOK * DDIM) {
        float s = 0.f;
        for (int e = 0; e < NEXP; e++) {
            float u = g_usage[e] / (float)NTOK;
            s += u * u;
        }
        out[NTOK * DDIM] = (float)NEXP * 0.01f * s;
    }
}

// ---------------- launch ----------------
extern "C" void kernel_launch(void* const* d_in, const int* in_sizes, int n_in,
                              void* d_out, int out_size) {
    const float* x  = (const float*)d_in[0];
    const float* rw = (const float*)d_in[1];
    const float* w1 = (const float*)d_in[2];
    const float* w2 = (const float*)d_in[3];
    const float* w3 = (const float*)d_in[4];
    float* out = (float*)d_out;

    init_kernel<<<1, 32>>>();
    router_kernel<<<NTOK / 8, 256>>>(x, rw);
    scan_kernel<<<1, 32>>>();
    build_kernel<<<(NTOK * KTOP + 255) / 256, 256>>>();
    gemm1_kernel<<<dim3(HDIM / 64, MAX_MT), 256>>>(x, w1, w3);
    gemm2_kernel<<<dim3(DDIM / 64, MAX_MT), 256>>>(w2);
    combine_kernel<<<(NTOK * (DDIM / 4) + 255) / 256, 256>>>(out);
    finalize_kernel<<<1, 32>>>(out, out_size);
}

// round 4
// speedup vs baseline: 2.3818x; 1.0014x over previous
#include <cuda_runtime.h>
#include <cuda_bf16.h>
#include <cstdint>

// ---------------- problem constants ----------------
#define NTOK   16384          // B*T = 8*2048
#define DDIM   512
#define HDIM   1408
#define NEXP   8
#define KTOP   2
#define NPAIR  (NTOK*KTOP)    // 32768
#define MAX_MT 520            // max 64-row M tiles across experts

// ---------------- device scratch (no allocations allowed) ----------------
__device__ float g_h[(size_t)NPAIR * HDIM];   // 184 MB intermediate h
__device__ float g_y[(size_t)NPAIR * DDIM];   // 67 MB per-pair expert output
__device__ int   g_tok_of_pair[NPAIR];
__device__ int   g_slot[NTOK * KTOP];
__device__ int   g_exp_of_tok[NTOK * KTOP];
__device__ float g_wt_of_tok[NTOK * KTOP];
__device__ int   g_counts[NEXP];
__device__ int   g_cursor[NEXP];
__device__ int   g_offsets[NEXP + 1];
__device__ float g_usage[NEXP];
__device__ int   g_tile_expert[MAX_MT];
__device__ int   g_tile_row[MAX_MT];
__device__ int   g_ntiles;

// ---------------- tf32 helpers ----------------
__device__ __forceinline__ uint32_t f2tf32(float f) {
    uint32_t u;
    asm("cvt.rna.tf32.f32 %0, %1;" : "=r"(u) : "f"(f));
    return u;
}

__device__ __forceinline__ void mma_tf32(float* c, const uint32_t* a, const uint32_t* b) {
    asm volatile(
        "mma.sync.aligned.m16n8k8.row.col.f32.tf32.tf32.f32 "
        "{%0,%1,%2,%3}, {%4,%5,%6,%7}, {%8,%9}, {%0,%1,%2,%3};\n"
        : "+f"(c[0]), "+f"(c[1]), "+f"(c[2]), "+f"(c[3])
        : "r"(a[0]), "r"(a[1]), "r"(a[2]), "r"(a[3]), "r"(b[0]), "r"(b[1]));
}

// ---------------- init ----------------
__global__ void init_kernel() {
    int i = threadIdx.x;
    if (i < NEXP) { g_counts[i] = 0; g_cursor[i] = 0; g_usage[i] = 0.f; }
}

// ---------------- router: warp per token ----------------
__global__ void __launch_bounds__(256) router_kernel(const float* __restrict__ x,
                                                     const float* __restrict__ rw) {
    int warp = threadIdx.x >> 5, lane = threadIdx.x & 31;
    int tok = blockIdx.x * 8 + warp;
    if (tok >= NTOK) return;
    const float* xr = x + (size_t)tok * DDIM;

    float xv[16];
#pragma unroll
    for (int i = 0; i < 16; i++) xv[i] = xr[lane + 32 * i];

    float logits[NEXP];
#pragma unroll
    for (int e = 0; e < NEXP; e++) {
        const float* wr = rw + e * DDIM;
        float s = 0.f;
#pragma unroll
        for (int i = 0; i < 16; i++) s += xv[i] * wr[lane + 32 * i];
#pragma unroll
        for (int o = 16; o > 0; o >>= 1) s += __shfl_xor_sync(0xffffffffu, s, o);
        logits[e] = s;
    }
    if (lane == 0) {
        float m = logits[0];
#pragma unroll
        for (int e = 1; e < NEXP; e++) m = fmaxf(m, logits[e]);
        float p[NEXP], Z = 0.f;
#pragma unroll
        for (int e = 0; e < NEXP; e++) { p[e] = __expf(logits[e] - m); Z += p[e]; }
        float inv = 1.f / Z;
        int a = 0;
#pragma unroll
        for (int e = 1; e < NEXP; e++) if (p[e] > p[a]) a = e;
        int b = (a == 0) ? 1 : 0;
#pragma unroll
        for (int e = 0; e < NEXP; e++) { if (e == a) continue; if (p[e] > p[b]) b = e; }
        float pa = p[a] * inv, pb = p[b] * inv;
        float wsum = pa + pb;
        g_exp_of_tok[tok * 2 + 0] = a;
        g_exp_of_tok[tok * 2 + 1] = b;
        g_wt_of_tok[tok * 2 + 0] = pa / wsum;
        g_wt_of_tok[tok * 2 + 1] = pb / wsum;
        atomicAdd(&g_counts[a], 1);
        atomicAdd(&g_counts[b], 1);
#pragma unroll
        for (int e = 0; e < NEXP; e++) atomicAdd(&g_usage[e], p[e] * inv);
    }
}

// ---------------- scan + tile descriptor list ----------------
__global__ void scan_kernel() {
    if (threadIdx.x != 0) return;
    int off = 0;
    for (int e = 0; e < NEXP; e++) { g_offsets[e] = off; off += g_counts[e]; }
    g_offsets[NEXP] = off;
    int nt = 0;
    for (int e = 0; e < NEXP; e++) {
        int cnt = g_counts[e];
        for (int r = 0; r < cnt; r += 64) {
            g_tile_expert[nt] = e;
            g_tile_row[nt] = g_offsets[e] + r;
            nt++;
        }
    }
    g_ntiles = nt;
}

// ---------------- build grouped pair arrays ----------------
__global__ void build_kernel() {
    int i = blockIdx.x * blockDim.x + threadIdx.x;
    if (i >= NTOK * KTOP) return;
    int e = g_exp_of_tok[i];
    int pos = g_offsets[e] + atomicAdd(&g_cursor[e], 1);
    g_tok_of_pair[pos] = i >> 1;
    g_slot[i] = pos;
}

// ============================================================
// GEMM1 (tf32 tensor cores): h = silu(x@w1^T) * (x@w3^T)
// CTA tile 64(M pairs) x 64(N h-cols), BK=32, 8 warps (32x16 each).
// ============================================================
#define SSTRIDE 36   // smem row stride (floats) -> conflict-free fragment LDS

__global__ void __launch_bounds__(256) gemm1_kernel(const float* __restrict__ x,
                                                    const float* __restrict__ w1,
                                                    const float* __restrict__ w3) {
    int mt = blockIdx.y;
    if (mt >= g_ntiles) return;
    int e = g_tile_expert[mt];
    int row0 = g_tile_row[mt];
    int valid = g_offsets[e + 1] - row0; if (valid > 64) valid = 64;
    int n0 = blockIdx.x * 64;

    const float* W1 = w1 + (size_t)e * HDIM * DDIM + (size_t)n0 * DDIM;
    const float* W3 = w3 + (size_t)e * HDIM * DDIM + (size_t)n0 * DDIM;

    __shared__ uint32_t As[64 * SSTRIDE];
    __shared__ uint32_t B1s[64 * SSTRIDE];
    __shared__ uint32_t B3s[64 * SSTRIDE];

    int tid = threadIdx.x;
    int lane = tid & 31, w = tid >> 5;
    int wm = (w & 1) * 32, wn = (w >> 1) * 16;
    int gid = lane >> 2, tig = lane & 3;

    // loader mapping: row = tid>>2 (0..63), cols [lc, lc+8)
    int lr = tid >> 2;
    int lc = (tid & 3) * 8;
    const float* arow = nullptr;
    if (lr < valid) arow = x + (size_t)g_tok_of_pair[row0 + lr] * DDIM;
    const float* b1row = W1 + (size_t)lr * DDIM;
    const float* b3row = W3 + (size_t)lr * DDIM;

    float acc1[2][2][4] = {}, acc3[2][2][4] = {};

    float4 ra[2], rb1[2], rb3[2];
    // prefetch chunk 0
    {
        ra[0] = ra[1] = make_float4(0.f, 0.f, 0.f, 0.f);
        if (arow) { ra[0] = *(const float4*)(arow + lc); ra[1] = *(const float4*)(arow + lc + 4); }
        rb1[0] = *(const float4*)(b1row + lc); rb1[1] = *(const float4*)(b1row + lc + 4);
        rb3[0] = *(const float4*)(b3row + lc); rb3[1] = *(const float4*)(b3row + lc + 4);
    }

    const int NC = DDIM / 32;   // 16 chunks
    for (int kc = 0; kc < NC; kc++) {
        __syncthreads();
        // store prefetched chunk with tf32 rounding
        uint32_t* Ar = As + lr * SSTRIDE + lc;
        uint32_t* B1r = B1s + lr * SSTRIDE + lc;
        uint32_t* B3r = B3s + lr * SSTRIDE + lc;
        Ar[0] = f2tf32(ra[0].x); Ar[1] = f2tf32(ra[0].y); Ar[2] = f2tf32(ra[0].z); Ar[3] = f2tf32(ra[0].w);
        Ar[4] = f2tf32(ra[1].x); Ar[5] = f2tf32(ra[1].y); Ar[6] = f2tf32(ra[1].z); Ar[7] = f2tf32(ra[1].w);
        B1r[0] = f2tf32(rb1[0].x); B1r[1] = f2tf32(rb1[0].y); B1r[2] = f2tf32(rb1[0].z); B1r[3] = f2tf32(rb1[0].w);
        B1r[4] = f2tf32(rb1[1].x); B1r[5] = f2tf32(rb1[1].y); B1r[6] = f2tf32(rb1[1].z); B1r[7] = f2tf32(rb1[1].w);
        B3r[0] = f2tf32(rb3[0].x); B3r[1] = f2tf32(rb3[0].y); B3r[2] = f2tf32(rb3[0].z); B3r[3] = f2tf32(rb3[0].w);
        B3r[4] = f2tf32(rb3[1].x); B3r[5] = f2tf32(rb3[1].y); B3r[6] = f2tf32(rb3[1].z); B3r[7] = f2tf32(rb3[1].w);
        __syncthreads();

        // prefetch next chunk (overlaps with mma below)
        if (kc + 1 < NC) {
            int k0 = (kc + 1) * 32;
            ra[0] = ra[1] = make_float4(0.f, 0.f, 0.f, 0.f);
            if (arow) { ra[0] = *(const float4*)(arow + k0 + lc); ra[1] = *(const float4*)(arow + k0 + lc + 4); }
            rb1[0] = *(const float4*)(b1row + k0 + lc); rb1[1] = *(const float4*)(b1row + k0 + lc + 4);
            rb3[0] = *(const float4*)(b3row + k0 + lc); rb3[1] = *(const float4*)(b3row + k0 + lc + 4);
        }

#pragma unroll
        for (int kk = 0; kk < 4; kk++) {
            int k = kk * 8;
            uint32_t afr[2][4];
#pragma unroll
            for (int m = 0; m < 2; m++) {
                int r = wm + m * 16 + gid;
                afr[m][0] = As[r * SSTRIDE + k + tig];
                afr[m][1] = As[(r + 8) * SSTRIDE + k + tig];
                afr[m][2] = As[r * SSTRIDE + k + tig + 4];
                afr[m][3] = As[(r + 8) * SSTRIDE + k + tig + 4];
            }
#pragma unroll
            for (int n = 0; n < 2; n++) {
                int c = wn + n * 8 + gid;
                uint32_t b1f[2] = { B1s[c * SSTRIDE + k + tig], B1s[c * SSTRIDE + k + tig + 4] };
                uint32_t b3f[2] = { B3s[c * SSTRIDE + k + tig], B3s[c * SSTRIDE + k + tig + 4] };
#pragma unroll
                for (int m = 0; m < 2; m++) {
                    mma_tf32(acc1[m][n], afr[m], b1f);
                    mma_tf32(acc3[m][n], afr[m], b3f);
                }
            }
        }
    }

    // epilogue: h = silu(acc1) * acc3
#pragma unroll
    for (int m = 0; m < 2; m++) {
#pragma unroll
        for (int n = 0; n < 2; n++) {
            int col = n0 + wn + n * 8 + 2 * tig;
#pragma unroll
            for (int half = 0; half < 2; half++) {
                int r = wm + m * 16 + gid + half * 8;
                if (r < valid) {
                    float* hr = g_h + (size_t)(row0 + r) * HDIM + col;
                    float z0 = acc1[m][n][half * 2 + 0];
                    float z1 = acc1[m][n][half * 2 + 1];
                    float s0 = z0 / (1.f + __expf(-z0));
                    float s1 = z1 / (1.f + __expf(-z1));
                    hr[0] = s0 * acc3[m][n][half * 2 + 0];
                    hr[1] = s1 * acc3[m][n][half * 2 + 1];
                }
            }
        }
    }
}

// ============================================================
// GEMM2 (tf32 tensor cores): y = h @ w2^T
// CTA tile 64 x 64, BK=32, K=1408 (44 chunks)
// ============================================================
__global__ void __launch_bounds__(256) gemm2_kernel(const float* __restrict__ w2) {
    int mt = blockIdx.y;
    if (mt >= g_ntiles) return;
    int e = g_tile_expert[mt];
    int row0 = g_tile_row[mt];
    int valid = g_offsets[e + 1] - row0; if (valid > 64) valid = 64;
    int n0 = blockIdx.x * 64;

    const float* W2 = w2 + (size_t)e * DDIM * HDIM + (size_t)n0 * HDIM;

    __shared__ uint32_t As[64 * SSTRIDE];
    __shared__ uint32_t Bs[64 * SSTRIDE];

    int tid = threadIdx.x;
    int lane = tid & 31, w = tid >> 5;
    int wm = (w & 1) * 32, wn = (w >> 1) * 16;
    int gid = lane >> 2, tig = lane & 3;

    int lr = tid >> 2;
    int lc = (tid & 3) * 8;
    const float* arow = (lr < valid) ? (g_h + (size_t)(row0 + lr) * HDIM) : nullptr;
    const float* brow = W2 + (size_t)lr * HDIM;

    float acc[2][2][4] = {};

    float4 ra[2], rb[2];
    {
        ra[0] = ra[1] = make_float4(0.f, 0.f, 0.f, 0.f);
        if (arow) { ra[0] = *(const float4*)(arow + lc); ra[1] = *(const float4*)(arow + lc + 4); }
        rb[0] = *(const float4*)(brow + lc); rb[1] = *(const float4*)(brow + lc + 4);
    }

    const int NC = HDIM / 32;   // 44 chunks
    for (int kc = 0; kc < NC; kc++) {
        __syncthreads();
        uint32_t* Ar = As + lr * SSTRIDE + lc;
        uint32_t* Br = Bs + lr * SSTRIDE + lc;
        Ar[0] = f2tf32(ra[0].x); Ar[1] = f2tf32(ra[0].y); Ar[2] = f2tf32(ra[0].z); Ar[3] = f2tf32(ra[0].w);
        Ar[4] = f2tf32(ra[1].x); Ar[5] = f2tf32(ra[1].y); Ar[6] = f2tf32(ra[1].z); Ar[7] = f2tf32(ra[1].w);
        Br[0] = f2tf32(rb[0].x); Br[1] = f2tf32(rb[0].y); Br[2] = f2tf32(rb[0].z); Br[3] = f2tf32(rb[0].w);
        Br[4] = f2tf32(rb[1].x); Br[5] = f2tf32(rb[1].y); Br[6] = f2tf32(rb[1].z); Br[7] = f2tf32(rb[1].w);
        __syncthreads();

        if (kc + 1 < NC) {
            int k0 = (kc + 1) * 32;
            ra[0] = ra[1] = make_float4(0.f, 0.f, 0.f, 0.f);
            if (arow) { ra[0] = *(const float4*)(arow + k0 + lc); ra[1] = *(const float4*)(arow + k0 + lc + 4); }
            rb[0] = *(const float4*)(brow + k0 + lc); rb[1] = *(const float4*)(brow + k0 + lc + 4);
        }

#pragma unroll
        for (int kk = 0; kk < 4; kk++) {
            int k = kk * 8;
            uint32_t afr[2][4];
#pragma unroll
            for (int m = 0; m < 2; m++) {
                int r = wm + m * 16 + gid;
                afr[m][0] = As[r * SSTRIDE + k + tig];
                afr[m][1] = As[(r + 8) * SSTRIDE + k + tig];
                afr[m][2] = As[r * SSTRIDE + k + tig + 4];
                afr[m][3] = As[(r + 8) * SSTRIDE + k + tig + 4];
            }
#pragma unroll
            for (int n = 0; n < 2; n++) {
                int c = wn + n * 8 + gid;
                uint32_t bf[2] = { Bs[c * SSTRIDE + k + tig], Bs[c * SSTRIDE + k + tig + 4] };
#pragma unroll
                for (int m = 0; m < 2; m++) {
                    mma_tf32(acc[m][n], afr[m], bf);
                }
            }
        }
    }

#pragma unroll
    for (int m = 0; m < 2; m++) {
#pragma unroll
        for (int n = 0; n < 2; n++) {
            int col = n0 + wn + n * 8 + 2 * tig;
#pragma unroll
            for (int half = 0; half < 2; half++) {
                int r = wm + m * 16 + gid + half * 8;
                if (r < valid) {
                    float* yr = g_y + (size_t)(row0 + r) * DDIM + col;
                    yr[0] = acc[m][n][half * 2 + 0];
                    yr[1] = acc[m][n][half * 2 + 1];
                }
            }
        }
    }
}

// ---------------- combine: out[tok] = w0*y[slot0] + w1*y[slot1] ----------------
__global__ void combine_kernel(float* __restrict__ out) {
    int i = blockIdx.x * blockDim.x + threadIdx.x;
    const int D4 = DDIM / 4;
    if (i >= NTOK * D4) return;
    int tok = i / D4;
    int d4 = i - tok * D4;
    int s0 = g_slot[tok * 2 + 0], s1 = g_slot[tok * 2 + 1];
    float w0 = g_wt_of_tok[tok * 2 + 0], w1 = g_wt_of_tok[tok * 2 + 1];
    const float4* y4 = (const float4*)g_y;
    float4 a = y4[(size_t)s0 * D4 + d4];
    float4 b = y4[(size_t)s1 * D4 + d4];
    float4 r;
    r.x = w0 * a.x + w1 * b.x;
    r.y = w0 * a.y + w1 * b.y;
    r.z = w0 * a.z + w1 * b.z;
    r.w = w0 * a.w + w1 * b.w;
    ((float4*)out)[i] = r;
}

// ---------------- aux loss ----------------
__global__ void finalize_kernel(float* __restrict__ out, int out_size) {
    if (threadIdx.x != 0 || blockIdx.x != 0) return;
    if (out_size > NTOK * DDIM) {
        float s = 0.f;
        for (int e = 0; e < NEXP; e++) {
            float u = g_usage[e] / (float)NTOK;
            s += u * u;
        }
        out[NTOK * DDIM] = (float)NEXP * 0.01f * s;
    }
}

// ---------------- launch ----------------
extern "C" void kernel_launch(void* const* d_in, const int* in_sizes, int n_in,
                              void* d_out, int out_size) {
    const float* x  = (const float*)d_in[0];
    const float* rw = (const float*)d_in[1];
    const float* w1 = (const float*)d_in[2];
    const float* w2 = (const float*)d_in[3];
    const float* w3 = (const float*)d_in[4];
    float* out = (float*)d_out;

    init_kernel<<<1, 32>>>();
    router_kernel<<<NTOK / 8, 256>>>(x, rw);
    scan_kernel<<<1, 32>>>();
    build_kernel<<<(NTOK * KTOP + 255) / 256, 256>>>();
    gemm1_kernel<<<dim3(HDIM / 64, MAX_MT), 256>>>(x, w1, w3);
    gemm2_kernel<<<dim3(DDIM / 64, MAX_MT), 256>>>(w2);
    combine_kernel<<<(NTOK * (DDIM / 4) + 255) / 256, 256>>>(out);
    finalize_kernel<<<1, 32>>>(out, out_size);
}

// round 8
// speedup vs baseline: 3.3477x; 1.4055x over previous
#include <cuda_runtime.h>
#include <cstdint>

// ---------------- problem constants ----------------
#define NTOK   16384
#define DDIM   512
#define HDIM   1408
#define NEXP   8
#define KTOP   2
#define NPAIR  (NTOK*KTOP)
#define MTILE  128            // M rows per CTA tile
#define MAX_MT 264            // sum ceil(cnt_e/128) <= 256 + 8

// ---------------- device scratch ----------------
__device__ uint32_t g_xt [(size_t)NTOK * DDIM];         // tf32(x)
__device__ uint32_t g_w1t[(size_t)NEXP * HDIM * DDIM];  // tf32(w1)
__device__ uint32_t g_w3t[(size_t)NEXP * HDIM * DDIM];  // tf32(w3)
__device__ uint32_t g_w2t[(size_t)NEXP * DDIM * HDIM];  // tf32(w2)
__device__ uint32_t g_h  [(size_t)NPAIR * HDIM];        // tf32(h)
__device__ float    g_y  [(size_t)NPAIR * DDIM];
__device__ int      g_tok_of_pair[NPAIR];
__device__ int      g_slot[NTOK * KTOP];
__device__ int      g_exp_of_tok[NTOK * KTOP];
__device__ float    g_wt_of_tok[NTOK * KTOP];
__device__ int      g_counts[NEXP];
__device__ int      g_cursor[NEXP];
__device__ int      g_offsets[NEXP + 1];
__device__ float    g_usage[NEXP];
__device__ int      g_tile_expert[MAX_MT];
__device__ int      g_tile_row[MAX_MT];
__device__ int      g_ntiles;

// ---------------- helpers ----------------
__device__ __forceinline__ uint32_t f2tf32(float f) {
    uint32_t u; asm("cvt.rna.tf32.f32 %0, %1;" : "=r"(u) : "f"(f)); return u;
}
__device__ __forceinline__ uint32_t smem_u32(const void* p) {
    uint32_t a;
    asm("{ .reg .u64 t; cvta.to.shared.u64 t, %1; cvt.u32.u64 %0, t; }" : "=r"(a) : "l"(p));
    return a;
}
__device__ __forceinline__ void cp16(uint32_t dst, const uint32_t* src) {
    asm volatile("cp.async.cg.shared.global [%0], [%1], 16;" :: "r"(dst), "l"(src));
}
#define CP_COMMIT() asm volatile("cp.async.commit_group;" ::: "memory")
#define CP_WAIT1()  asm volatile("cp.async.wait_group 1;" ::: "memory")
#define SWZ(x) ((x) ^ (((x) >> 3) & 0x70))

#define LDSM4(r0, r1, r2, r3, addr) \
    asm volatile("ldmatrix.sync.aligned.m8n8.x4.shared.b16 {%0,%1,%2,%3}, [%4];" \
        : "=r"(r0), "=r"(r1), "=r"(r2), "=r"(r3) : "r"(addr))

__device__ __forceinline__ void mma_tf32(float* c, const uint32_t* a, const uint32_t* b) {
    asm volatile(
        "mma.sync.aligned.m16n8k8.row.col.f32.tf32.tf32.f32 "
        "{%0,%1,%2,%3}, {%4,%5,%6,%7}, {%8,%9}, {%0,%1,%2,%3};\n"
        : "+f"(c[0]), "+f"(c[1]), "+f"(c[2]), "+f"(c[3])
        : "r"(a[0]), "r"(a[1]), "r"(a[2]), "r"(a[3]), "r"(b[0]), "r"(b[1]));
}

// ---------------- small kernels (verified R3) ----------------
__global__ void init_kernel() {
    int i = threadIdx.x;
    if (i < NEXP) { g_counts[i] = 0; g_cursor[i] = 0; g_usage[i] = 0.f; }
}

__global__ void __launch_bounds__(256) router_kernel(const float* __restrict__ x,
                                                     const float* __restrict__ rw) {
    int warp = threadIdx.x >> 5, lane = threadIdx.x & 31;
    int tok = blockIdx.x * 8 + warp;
    if (tok >= NTOK) return;
    const float* xr = x + (size_t)tok * DDIM;
    float xv[16];
#pragma unroll
    for (int i = 0; i < 16; i++) xv[i] = xr[lane + 32 * i];
    float logits[NEXP];
#pragma unroll
    for (int e = 0; e < NEXP; e++) {
        const float* wr = rw + e * DDIM;
        float s = 0.f;
#pragma unroll
        for (int i = 0; i < 16; i++) s += xv[i] * wr[lane + 32 * i];
#pragma unroll
        for (int o = 16; o > 0; o >>= 1) s += __shfl_xor_sync(0xffffffffu, s, o);
        logits[e] = s;
    }
    if (lane == 0) {
        float m = logits[0];
#pragma unroll
        for (int e = 1; e < NEXP; e++) m = fmaxf(m, logits[e]);
        float p[NEXP], Z = 0.f;
#pragma unroll
        for (int e = 0; e < NEXP; e++) { p[e] = __expf(logits[e] - m); Z += p[e]; }
        float inv = 1.f / Z;
        int a = 0;
#pragma unroll
        for (int e = 1; e < NEXP; e++) if (p[e] > p[a]) a = e;
        int b = (a == 0) ? 1 : 0;
#pragma unroll
        for (int e = 0; e < NEXP; e++) { if (e == a) continue; if (p[e] > p[b]) b = e; }
        float pa = p[a] * inv, pb = p[b] * inv, ws = pa + pb;
        g_exp_of_tok[tok * 2 + 0] = a;
        g_exp_of_tok[tok * 2 + 1] = b;
        g_wt_of_tok[tok * 2 + 0] = pa / ws;
        g_wt_of_tok[tok * 2 + 1] = pb / ws;
        atomicAdd(&g_counts[a], 1);
        atomicAdd(&g_counts[b], 1);
#pragma unroll
        for (int e = 0; e < NEXP; e++) atomicAdd(&g_usage[e], p[e] * inv);
    }
}

__global__ void scan_kernel() {
    if (threadIdx.x != 0) return;
    int off = 0;
    for (int e = 0; e < NEXP; e++) { g_offsets[e] = off; off += g_counts[e]; }
    g_offsets[NEXP] = off;
    int nt = 0;
    for (int e = 0; e < NEXP; e++) {
        int cnt = g_counts[e];
        for (int r = 0; r < cnt; r += MTILE) {
            g_tile_expert[nt] = e;
            g_tile_row[nt] = g_offsets[e] + r;
            nt++;
        }
    }
    g_ntiles = nt;
}

__global__ void build_kernel() {
    int i = blockIdx.x * blockDim.x + threadIdx.x;
    if (i >= NTOK * KTOP) return;
    int e = g_exp_of_tok[i];
    int pos = g_offsets[e] + atomicAdd(&g_cursor[e], 1);
    g_tok_of_pair[pos] = i >> 1;
    g_slot[i] = pos;
}

__global__ void cvt_kernel(const float4* __restrict__ src, uint4* __restrict__ dst, int n4) {
    int i = blockIdx.x * blockDim.x + threadIdx.x;
    if (i >= n4) return;
    float4 v = src[i];
    uint4 o;
    o.x = f2tf32(v.x); o.y = f2tf32(v.y); o.z = f2tf32(v.z); o.w = f2tf32(v.w);
    dst[i] = o;
}

// ============================================================
// GEMM mainloop config: CTA 128M, BK=32, 3-stage cp.async,
// SW128-swizzled smem, ldmatrix fragment loads.
// Stage layout: A [128 rows x 128B] @0, B [128 rows x 128B] @16K.
// ============================================================
#define BK        32
#define NSTG      3
#define STG_BYTES 32768
#define BOFF      16384
#define GSMEM     (NSTG * STG_BYTES)   // 96 KB

// ---------------- GEMM1: h = silu(x@w1^T)*(x@w3^T) ----------------
// CTA 128M x 64N(per matrix); B smem rows 0-63 = w1, 64-127 = w3.
// 8 warps: 4(M) x 2(N); warp = 32M x 32N dual.
__global__ void __launch_bounds__(256, 2) gemm1_mm() {
    extern __shared__ char smem[];
    int mt = blockIdx.y;
    if (mt >= g_ntiles) return;
    int e = g_tile_expert[mt];
    int row0 = g_tile_row[mt];
    int valid = g_offsets[e + 1] - row0; if (valid > MTILE) valid = MTILE;
    int n0 = blockIdx.x * 64;

    uint32_t sb = smem_u32(smem);
    int tid = threadIdx.x;

    // loaders: thread -> row tid>>1, 64B half tid&1 (4 x cp16 each for A and B)
    int lr = tid >> 1, half = tid & 1;
    int aidx = row0 + lr; if (aidx >= NPAIR) aidx = NPAIR - 1;
    const uint32_t* asrc = g_xt + (size_t)g_tok_of_pair[aidx] * DDIM + half * 16;
    const uint32_t* bsrc = (lr < 64)
        ? g_w1t + (size_t)e * HDIM * DDIM + (size_t)(n0 + lr) * DDIM + half * 16
        : g_w3t + (size_t)e * HDIM * DDIM + (size_t)(n0 + lr - 64) * DDIM + half * 16;
    uint32_t abase = lr * 128 + half * 64;

#define G1_LD(kc, st) do { \
    uint32_t _s = sb + (st) * STG_BYTES; \
    const uint32_t* _a = asrc + (kc) * BK; \
    const uint32_t* _b = bsrc + (kc) * BK; \
    _Pragma("unroll") for (int c = 0; c < 4; c++) { \
        cp16(_s + SWZ(abase + c * 16), _a + c * 4); \
        cp16(_s + BOFF + SWZ(abase + c * 16), _b + c * 4); \
    } \
    CP_COMMIT(); \
} while (0)

    int w = tid >> 5, lane = tid & 31;
    int wm = (w & 3) * 32, wn = (w >> 2) * 32;
    int l7 = lane & 7;
    int rA = wm + l7 + ((lane >> 3) & 1) * 8;      // A ldmatrix row
    int cA = (lane >> 4) * 16;                     // A k-half byte
    int rB = l7 + ((lane >> 4) & 1) * 8;           // B ldmatrix row (rel)
    int cB = ((lane >> 3) & 1) * 16;               // B k-half byte

    float acc1[2][4][4] = {}, acc3[2][4][4] = {};

    G1_LD(0, 0);
    G1_LD(1, 1);
    const int NC = DDIM / BK;   // 16
    for (int kc = 0; kc < NC; kc++) {
        int st = kc % NSTG;
        CP_WAIT1();
        __syncthreads();
        if (kc + 2 < NC) G1_LD(kc + 2, (kc + 2) % NSTG); else CP_COMMIT();

        uint32_t sA = sb + st * STG_BYTES;
        uint32_t sB = sA + BOFF;
#pragma unroll
        for (int kk = 0; kk < 4; kk++) {
            uint32_t a[2][4];
#pragma unroll
            for (int m = 0; m < 2; m++)
                LDSM4(a[m][0], a[m][1], a[m][2], a[m][3],
                      sA + SWZ((rA + m * 16) * 128 + kk * 32 + cA));
            uint32_t b1[2][4], b3[2][4];
#pragma unroll
            for (int np = 0; np < 2; np++) {
                LDSM4(b1[np][0], b1[np][1], b1[np][2], b1[np][3],
                      sB + SWZ((wn + np * 16 + rB) * 128 + kk * 32 + cB));
                LDSM4(b3[np][0], b3[np][1], b3[np][2], b3[np][3],
                      sB + SWZ((64 + wn + np * 16 + rB) * 128 + kk * 32 + cB));
            }
#pragma unroll
            for (int m = 0; m < 2; m++)
#pragma unroll
                for (int np = 0; np < 2; np++)
#pragma unroll
                    for (int j = 0; j < 2; j++) {
                        mma_tf32(acc1[m][np * 2 + j], a[m], &b1[np][j * 2]);
                        mma_tf32(acc3[m][np * 2 + j], a[m], &b3[np][j * 2]);
                    }
        }
    }

    // epilogue: h = tf32(silu(acc1) * acc3)
    int gid = lane >> 2, tig = lane & 3;
#pragma unroll
    for (int m = 0; m < 2; m++)
#pragma unroll
        for (int no = 0; no < 4; no++) {
            int col = n0 + wn + no * 8 + 2 * tig;
#pragma unroll
            for (int hf = 0; hf < 2; hf++) {
                int r = wm + m * 16 + gid + hf * 8;
                if (r < valid) {
                    float z0 = acc1[m][no][hf * 2 + 0];
                    float z1 = acc1[m][no][hf * 2 + 1];
                    float s0 = z0 / (1.f + __expf(-z0));
                    float s1 = z1 / (1.f + __expf(-z1));
                    uint2 v;
                    v.x = f2tf32(s0 * acc3[m][no][hf * 2 + 0]);
                    v.y = f2tf32(s1 * acc3[m][no][hf * 2 + 1]);
                    *(uint2*)(g_h + (size_t)(row0 + r) * HDIM + col) = v;
                }
            }
        }
}

// ---------------- GEMM2: y = h @ w2^T ----------------
// CTA 128M x 128N; 8 warps 4(M) x 2(N); warp 32M x 64N; K=1408.
__global__ void __launch_bounds__(256, 2) gemm2_mm() {
    extern __shared__ char smem[];
    int mt = blockIdx.y;
    if (mt >= g_ntiles) return;
    int e = g_tile_expert[mt];
    int row0 = g_tile_row[mt];
    int valid = g_offsets[e + 1] - row0; if (valid > MTILE) valid = MTILE;
    int n0 = blockIdx.x * 128;

    uint32_t sb = smem_u32(smem);
    int tid = threadIdx.x;

    int lr = tid >> 1, half = tid & 1;
    int aidx = row0 + lr; if (aidx >= NPAIR) aidx = NPAIR - 1;
    const uint32_t* asrc = g_h + (size_t)aidx * HDIM + half * 16;
    const uint32_t* bsrc = g_w2t + (size_t)e * DDIM * HDIM + (size_t)(n0 + lr) * HDIM + half * 16;
    uint32_t abase = lr * 128 + half * 64;

#define G2_LD(kc, st) do { \
    uint32_t _s = sb + (st) * STG_BYTES; \
    const uint32_t* _a = asrc + (kc) * BK; \
    const uint32_t* _b = bsrc + (kc) * BK; \
    _Pragma("unroll") for (int c = 0; c < 4; c++) { \
        cp16(_s + SWZ(abase + c * 16), _a + c * 4); \
        cp16(_s + BOFF + SWZ(abase + c * 16), _b + c * 4); \
    } \
    CP_COMMIT(); \
} while (0)

    int w = tid >> 5, lane = tid & 31;
    int wm = (w & 3) * 32, wn = (w >> 2) * 64;
    int l7 = lane & 7;
    int rA = wm + l7 + ((lane >> 3) & 1) * 8;
    int cA = (lane >> 4) * 16;
    int rB = l7 + ((lane >> 4) & 1) * 8;
    int cB = ((lane >> 3) & 1) * 16;

    float acc[2][8][4] = {};

    G2_LD(0, 0);
    G2_LD(1, 1);
    const int NC = HDIM / BK;   // 44
    for (int kc = 0; kc < NC; kc++) {
        int st = kc % NSTG;
        CP_WAIT1();
        __syncthreads();
        if (kc + 2 < NC) G2_LD(kc + 2, (kc + 2) % NSTG); else CP_COMMIT();

        uint32_t sA = sb + st * STG_BYTES;
        uint32_t sB = sA + BOFF;
#pragma unroll
        for (int kk = 0; kk < 4; kk++) {
            uint32_t a[2][4];
#pragma unroll
            for (int m = 0; m < 2; m++)
                LDSM4(a[m][0], a[m][1], a[m][2], a[m][3],
                      sA + SWZ((rA + m * 16) * 128 + kk * 32 + cA));
            uint32_t b[4][4];
#pragma unroll
            for (int np = 0; np < 4; np++)
                LDSM4(b[np][0], b[np][1], b[np][2], b[np][3],
                      sB + SWZ((wn + np * 16 + rB) * 128 + kk * 32 + cB));
#pragma unroll
            for (int m = 0; m < 2; m++)
#pragma unroll
                for (int np = 0; np < 4; np++)
#pragma unroll
                    for (int j = 0; j < 2; j++)
                        mma_tf32(acc[m][np * 2 + j], a[m], &b[np][j * 2]);
        }
    }

    int gid = lane >> 2, tig = lane & 3;
#pragma unroll
    for (int m = 0; m < 2; m++)
#pragma unroll
        for (int no = 0; no < 8; no++) {
            int col = n0 + wn + no * 8 + 2 * tig;
#pragma unroll
            for (int hf = 0; hf < 2; hf++) {
                int r = wm + m * 16 + gid + hf * 8;
                if (r < valid) {
                    float2 v;
                    v.x = acc[m][no][hf * 2 + 0];
                    v.y = acc[m][no][hf * 2 + 1];
                    *(float2*)(g_y + (size_t)(row0 + r) * DDIM + col) = v;
                }
            }
        }
}

// ---------------- combine + aux ----------------
__global__ void combine_kernel(float* __restrict__ out) {
    int i = blockIdx.x * blockDim.x + threadIdx.x;
    const int D4 = DDIM / 4;
    if (i >= NTOK * D4) return;
    int tok = i / D4;
    int d4 = i - tok * D4;
    int s0 = g_slot[tok * 2 + 0], s1 = g_slot[tok * 2 + 1];
    float w0 = g_wt_of_tok[tok * 2 + 0], w1 = g_wt_of_tok[tok * 2 + 1];
    const float4* y4 = (const float4*)g_y;
    float4 a = y4[(size_t)s0 * D4 + d4];
    float4 b = y4[(size_t)s1 * D4 + d4];
    float4 r;
    r.x = w0 * a.x + w1 * b.x;
    r.y = w0 * a.y + w1 * b.y;
    r.z = w0 * a.z + w1 * b.z;
    r.w = w0 * a.w + w1 * b.w;
    ((float4*)out)[i] = r;
}

__global__ void finalize_kernel(float* __restrict__ out, int out_size) {
    if (threadIdx.x != 0 || blockIdx.x != 0) return;
    if (out_size > NTOK * DDIM) {
        float s = 0.f;
        for (int e = 0; e < NEXP; e++) {
            float u = g_usage[e] / (float)NTOK;
            s += u * u;
        }
        out[NTOK * DDIM] = (float)NEXP * 0.01f * s;
    }
}

// ---------------- launch ----------------
extern "C" void kernel_launch(void* const* d_in, const int* in_sizes, int n_in,
                              void* d_out, int out_size) {
    const float* x  = (const float*)d_in[0];
    const float* rw = (const float*)d_in[1];
    const float* w1 = (const float*)d_in[2];
    const float* w2 = (const float*)d_in[3];
    const float* w3 = (const float*)d_in[4];
    float* out = (float*)d_out;

    cudaFuncSetAttribute(gemm1_mm, cudaFuncAttributeMaxDynamicSharedMemorySize, GSMEM);
    cudaFuncSetAttribute(gemm2_mm, cudaFuncAttributeMaxDynamicSharedMemorySize, GSMEM);

    uint32_t* gxt;  cudaGetSymbolAddress((void**)&gxt,  g_xt);
    uint32_t* gw1;  cudaGetSymbolAddress((void**)&gw1,  g_w1t);
    uint32_t* gw3;  cudaGetSymbolAddress((void**)&gw3,  g_w3t);
    uint32_t* gw2;  cudaGetSymbolAddress((void**)&gw2,  g_w2t);

    init_kernel<<<1, 32>>>();
    router_kernel<<<NTOK / 8, 256>>>(x, rw);
    scan_kernel<<<1, 32>>>();
    build_kernel<<<(NTOK * KTOP + 255) / 256, 256>>>();

    int nx = NTOK * DDIM / 4, nw = NEXP * HDIM * DDIM / 4;
    cvt_kernel<<<(nx + 255) / 256, 256>>>((const float4*)x,  (uint4*)gxt, nx);
    cvt_kernel<<<(nw + 255) / 256, 256>>>((const float4*)w1, (uint4*)gw1, nw);
    cvt_kernel<<<(nw + 255) / 256, 256>>>((const float4*)w3, (uint4*)gw3, nw);
    cvt_kernel<<<(nw + 255) / 256, 256>>>((const float4*)w2, (uint4*)gw2, nw);

    gemm1_mm<<<dim3(HDIM / 64, MAX_MT), 256, GSMEM>>>();
    gemm2_mm<<<dim3(DDIM / 128, MAX_MT), 256, GSMEM>>>();
    combine_kernel<<<(NTOK * (DDIM / 4) + 255) / 256, 256>>>(out);
    finalize_kernel<<<1, 32>>>(out, out_size);
}

// round 9
// speedup vs baseline: 5.2997x; 1.5831x over previous
#include <cuda_runtime.h>
#include <cuda_fp16.h>
#include <cstdint>

// ---------------- problem constants ----------------
#define NTOK   16384
#define DDIM   512
#define HDIM   1408
#define NEXP   8
#define KTOP   2
#define NPAIR  (NTOK*KTOP)
#define MTILE  128            // M rows per CTA tile
#define MAX_MT 264            // sum ceil(cnt_e/128) <= 256 + 8

// ---------------- device scratch ----------------
__device__ __half g_xh [(size_t)NTOK * DDIM];         // fp16(x)
__device__ __half g_w1h[(size_t)NEXP * HDIM * DDIM];  // fp16(w1)
__device__ __half g_w3h[(size_t)NEXP * HDIM * DDIM];  // fp16(w3)
__device__ __half g_w2h[(size_t)NEXP * DDIM * HDIM];  // fp16(w2)
__device__ __half g_h  [(size_t)NPAIR * HDIM];        // fp16(h)
__device__ float  g_y  [(size_t)NPAIR * DDIM];
__device__ int    g_tok_of_pair[NPAIR];
__device__ int    g_slot[NTOK * KTOP];
__device__ int    g_exp_of_tok[NTOK * KTOP];
__device__ float  g_wt_of_tok[NTOK * KTOP];
__device__ int    g_counts[NEXP];
__device__ int    g_cursor[NEXP];
__device__ int    g_offsets[NEXP + 1];
__device__ float  g_usage[NEXP];
__device__ int    g_tile_expert[MAX_MT];
__device__ int    g_tile_row[MAX_MT];
__device__ int    g_ntiles;

// ---------------- helpers ----------------
__device__ __forceinline__ uint32_t smem_u32(const void* p) {
    uint32_t a;
    asm("{ .reg .u64 t; cvta.to.shared.u64 t, %1; cvt.u32.u64 %0, t; }" : "=r"(a) : "l"(p));
    return a;
}
__device__ __forceinline__ void cp16(uint32_t dst, const void* src) {
    asm volatile("cp.async.cg.shared.global [%0], [%1], 16;" :: "r"(dst), "l"(src));
}
#define CP_COMMIT() asm volatile("cp.async.commit_group;" ::: "memory")
#define CP_WAIT1()  asm volatile("cp.async.wait_group 1;" ::: "memory")
#define SWZ(x) ((x) ^ (((x) >> 3) & 0x70))

#define LDSM4(r0, r1, r2, r3, addr) \
    asm volatile("ldmatrix.sync.aligned.m8n8.x4.shared.b16 {%0,%1,%2,%3}, [%4];" \
        : "=r"(r0), "=r"(r1), "=r"(r2), "=r"(r3) : "r"(addr))

// m16n8k16 fp16 mma, fp32 accumulate
__device__ __forceinline__ void mma_f16(float* c, const uint32_t* a, const uint32_t* b) {
    asm volatile(
        "mma.sync.aligned.m16n8k16.row.col.f32.f16.f16.f32 "
        "{%0,%1,%2,%3}, {%4,%5,%6,%7}, {%8,%9}, {%0,%1,%2,%3};\n"
        : "+f"(c[0]), "+f"(c[1]), "+f"(c[2]), "+f"(c[3])
        : "r"(a[0]), "r"(a[1]), "r"(a[2]), "r"(a[3]), "r"(b[0]), "r"(b[1]));
}

// ---------------- small kernels (verified R3/R8) ----------------
__global__ void init_kernel() {
    int i = threadIdx.x;
    if (i < NEXP) { g_counts[i] = 0; g_cursor[i] = 0; g_usage[i] = 0.f; }
}

__global__ void __launch_bounds__(256) router_kernel(const float* __restrict__ x,
                                                     const float* __restrict__ rw) {
    int warp = threadIdx.x >> 5, lane = threadIdx.x & 31;
    int tok = blockIdx.x * 8 + warp;
    if (tok >= NTOK) return;
    const float* xr = x + (size_t)tok * DDIM;
    float xv[16];
#pragma unroll
    for (int i = 0; i < 16; i++) xv[i] = xr[lane + 32 * i];
    float logits[NEXP];
#pragma unroll
    for (int e = 0; e < NEXP; e++) {
        const float* wr = rw + e * DDIM;
        float s = 0.f;
#pragma unroll
        for (int i = 0; i < 16; i++) s += xv[i] * wr[lane + 32 * i];
#pragma unroll
        for (int o = 16; o > 0; o >>= 1) s += __shfl_xor_sync(0xffffffffu, s, o);
        logits[e] = s;
    }
    if (lane == 0) {
        float m = logits[0];
#pragma unroll
        for (int e = 1; e < NEXP; e++) m = fmaxf(m, logits[e]);
        float p[NEXP], Z = 0.f;
#pragma unroll
        for (int e = 0; e < NEXP; e++) { p[e] = __expf(logits[e] - m); Z += p[e]; }
        float inv = 1.f / Z;
        int a = 0;
#pragma unroll
        for (int e = 1; e < NEXP; e++) if (p[e] > p[a]) a = e;
        int b = (a == 0) ? 1 : 0;
#pragma unroll
        for (int e = 0; e < NEXP; e++) { if (e == a) continue; if (p[e] > p[b]) b = e; }
        float pa = p[a] * inv, pb = p[b] * inv, ws = pa + pb;
        g_exp_of_tok[tok * 2 + 0] = a;
        g_exp_of_tok[tok * 2 + 1] = b;
        g_wt_of_tok[tok * 2 + 0] = pa / ws;
        g_wt_of_tok[tok * 2 + 1] = pb / ws;
        atomicAdd(&g_counts[a], 1);
        atomicAdd(&g_counts[b], 1);
#pragma unroll
        for (int e = 0; e < NEXP; e++) atomicAdd(&g_usage[e], p[e] * inv);
    }
}

__global__ void scan_kernel() {
    if (threadIdx.x != 0) return;
    int off = 0;
    for (int e = 0; e < NEXP; e++) { g_offsets[e] = off; off += g_counts[e]; }
    g_offsets[NEXP] = off;
    int nt = 0;
    for (int e = 0; e < NEXP; e++) {
        int cnt = g_counts[e];
        for (int r = 0; r < cnt; r += MTILE) {
            g_tile_expert[nt] = e;
            g_tile_row[nt] = g_offsets[e] + r;
            nt++;
        }
    }
    g_ntiles = nt;
}

__global__ void build_kernel() {
    int i = blockIdx.x * blockDim.x + threadIdx.x;
    if (i >= NTOK * KTOP) return;
    int e = g_exp_of_tok[i];
    int pos = g_offsets[e] + atomicAdd(&g_cursor[e], 1);
    g_tok_of_pair[pos] = i >> 1;
    g_slot[i] = pos;
}

// fp32 -> fp16(rn): 8 floats per thread -> one 16B store
__global__ void cvt_kernel(const float4* __restrict__ src, uint4* __restrict__ dst, int n8) {
    int i = blockIdx.x * blockDim.x + threadIdx.x;
    if (i >= n8) return;
    float4 s0 = src[2 * i], s1 = src[2 * i + 1];
    __half2 h0 = __floats2half2_rn(s0.x, s0.y);
    __half2 h1 = __floats2half2_rn(s0.z, s0.w);
    __half2 h2 = __floats2half2_rn(s1.x, s1.y);
    __half2 h3 = __floats2half2_rn(s1.z, s1.w);
    uint4 o;
    o.x = *(uint32_t*)&h0; o.y = *(uint32_t*)&h1;
    o.z = *(uint32_t*)&h2; o.w = *(uint32_t*)&h3;
    dst[i] = o;
}

// ============================================================
// GEMM config: CTA 128M, BK=64 fp16 (128B rows), 3-stage cp.async,
// SW128 swizzle, ldmatrix b16 (native fp16), m16n8k16 mma.
// Stage: A [128 x 128B] @0, B [128 x 128B] @16K. 96 KB total.
// ============================================================
#define BK        64
#define NSTG      3
#define STG_BYTES 32768
#define BOFF      16384
#define GSMEM     (NSTG * STG_BYTES)

// ---------------- GEMM1: h = silu(x@w1^T)*(x@w3^T) ----------------
// CTA 128M x 64N per matrix; B smem rows 0-63 = w1, 64-127 = w3.
// 8 warps 4(M) x 2(N); warp = 32M x 32N dual.
__global__ void __launch_bounds__(256, 2) gemm1_mm() {
    extern __shared__ char smem[];
    int mt = blockIdx.y;
    if (mt >= g_ntiles) return;
    int e = g_tile_expert[mt];
    int row0 = g_tile_row[mt];
    int valid = g_offsets[e + 1] - row0; if (valid > MTILE) valid = MTILE;
    int n0 = blockIdx.x * 64;

    uint32_t sb = smem_u32(smem);
    int tid = threadIdx.x;

    // loaders: thread -> row tid>>1, 64B half tid&1 (4 cp16 each for A and B)
    int lr = tid >> 1, half = tid & 1;
    int aidx = row0 + lr; if (aidx >= NPAIR) aidx = NPAIR - 1;
    const __half* asrc = g_xh + (size_t)g_tok_of_pair[aidx] * DDIM + half * 32;
    const __half* bsrc = (lr < 64)
        ? g_w1h + (size_t)e * HDIM * DDIM + (size_t)(n0 + lr) * DDIM + half * 32
        : g_w3h + (size_t)e * HDIM * DDIM + (size_t)(n0 + lr - 64) * DDIM + half * 32;
    uint32_t abase = lr * 128 + half * 64;

#define G1_LD(kc, st) do { \
    uint32_t _s = sb + (st) * STG_BYTES; \
    const __half* _a = asrc + (kc) * BK; \
    const __half* _b = bsrc + (kc) * BK; \
    _Pragma("unroll") for (int c = 0; c < 4; c++) { \
        cp16(_s + SWZ(abase + c * 16), _a + c * 8); \
        cp16(_s + BOFF + SWZ(abase + c * 16), _b + c * 8); \
    } \
    CP_COMMIT(); \
} while (0)

    int w = tid >> 5, lane = tid & 31;
    int wm = (w & 3) * 32, wn = (w >> 2) * 32;
    int l7 = lane & 7;
    // A ldmatrix: m0/m1 rows, m2/m3 k+16B  (16x16 fp16 per LDSM4)
    int rA = l7 + ((lane >> 3) & 1) * 8;
    int cA = ((lane >> 4) & 1) * 16;
    // B ldmatrix: m0/m1 = n rows at k0/k+16B, m2/m3 = n+8
    int rB = l7 + ((lane >> 4) & 1) * 8;
    int cB = ((lane >> 3) & 1) * 16;

    float acc1[2][4][4] = {}, acc3[2][4][4] = {};

    G1_LD(0, 0);
    G1_LD(1, 1);
    const int NC = DDIM / BK;   // 8
    for (int kc = 0; kc < NC; kc++) {
        int st = kc % NSTG;
        CP_WAIT1();
        __syncthreads();
        if (kc + 2 < NC) G1_LD(kc + 2, (kc + 2) % NSTG); else CP_COMMIT();

        uint32_t sA = sb + st * STG_BYTES;
        uint32_t sB = sA + BOFF;
#pragma unroll
        for (int kk = 0; kk < 4; kk++) {     // k16 steps (32B each)
            uint32_t a[2][4];
#pragma unroll
            for (int m = 0; m < 2; m++)
                LDSM4(a[m][0], a[m][1], a[m][2], a[m][3],
                      sA + SWZ((wm + m * 16 + rA) * 128 + kk * 32 + cA));
            uint32_t b1[2][4], b3[2][4];     // [n16 group][2 frags x 2 regs]
#pragma unroll
            for (int np = 0; np < 2; np++) {
                LDSM4(b1[np][0], b1[np][1], b1[np][2], b1[np][3],
                      sB + SWZ((wn + np * 16 + rB) * 128 + kk * 32 + cB));
                LDSM4(b3[np][0], b3[np][1], b3[np][2], b3[np][3],
                      sB + SWZ((64 + wn + np * 16 + rB) * 128 + kk * 32 + cB));
            }
#pragma unroll
            for (int m = 0; m < 2; m++)
#pragma unroll
                for (int np = 0; np < 2; np++)
#pragma unroll
                    for (int j = 0; j < 2; j++) {   // n8 within n16: frag {r0,r1} / {r2,r3}
                        mma_f16(acc1[m][np * 2 + j], a[m], &b1[np][j * 2]);
                        mma_f16(acc3[m][np * 2 + j], a[m], &b3[np][j * 2]);
                    }
        }
    }

    // epilogue: h = fp16(silu(acc1) * acc3)
    int gid = lane >> 2, tig = lane & 3;
#pragma unroll
    for (int m = 0; m < 2; m++)
#pragma unroll
        for (int no = 0; no < 4; no++) {
            int col = n0 + wn + no * 8 + 2 * tig;
#pragma unroll
            for (int hf = 0; hf < 2; hf++) {
                int r = wm + m * 16 + gid + hf * 8;
                if (r < valid) {
                    float z0 = acc1[m][no][hf * 2 + 0];
                    float z1 = acc1[m][no][hf * 2 + 1];
                    float s0 = z0 / (1.f + __expf(-z0));
                    float s1 = z1 / (1.f + __expf(-z1));
                    __half2 v = __floats2half2_rn(s0 * acc3[m][no][hf * 2 + 0],
                                                  s1 * acc3[m][no][hf * 2 + 1]);
                    *(__half2*)(g_h + (size_t)(row0 + r) * HDIM + col) = v;
                }
            }
        }
}

// ---------------- GEMM2: y = h @ w2^T ----------------
// CTA 128M x 128N; 8 warps 4(M) x 2(N); warp 32M x 64N; K=1408.
__global__ void __launch_bounds__(256, 2) gemm2_mm() {
    extern __shared__ char smem[];
    int mt = blockIdx.y;
    if (mt >= g_ntiles) return;
    int e = g_tile_expert[mt];
    int row0 = g_tile_row[mt];
    int valid = g_offsets[e + 1] - row0; if (valid > MTILE) valid = MTILE;
    int n0 = blockIdx.x * 128;

    uint32_t sb = smem_u32(smem);
    int tid = threadIdx.x;

    int lr = tid >> 1, half = tid & 1;
    int aidx = row0 + lr; if (aidx >= NPAIR) aidx = NPAIR - 1;
    const __half* asrc = g_h + (size_t)aidx * HDIM + half * 32;
    const __half* bsrc = g_w2h + (size_t)e * DDIM * HDIM + (size_t)(n0 + lr) * HDIM + half * 32;
    uint32_t abase = lr * 128 + half * 64;

#define G2_LD(kc, st) do { \
    uint32_t _s = sb + (st) * STG_BYTES; \
    const __half* _a = asrc + (kc) * BK; \
    const __half* _b = bsrc + (kc) * BK; \
    _Pragma("unroll") for (int c = 0; c < 4; c++) { \
        cp16(_s + SWZ(abase + c * 16), _a + c * 8); \
        cp16(_s + BOFF + SWZ(abase + c * 16), _b + c * 8); \
    } \
    CP_COMMIT(); \
} while (0)

    int w = tid >> 5, lane = tid & 31;
    int wm = (w & 3) * 32, wn = (w >> 2) * 64;
    int l7 = lane & 7;
    int rA = l7 + ((lane >> 3) & 1) * 8;
    int cA = ((lane >> 4) & 1) * 16;
    int rB = l7 + ((lane >> 4) & 1) * 8;
    int cB = ((lane >> 3) & 1) * 16;

    float acc[2][8][4] = {};

    G2_LD(0, 0);
    G2_LD(1, 1);
    const int NC = HDIM / BK;   // 22
    for (int kc = 0; kc < NC; kc++) {
        int st = kc % NSTG;
        CP_WAIT1();
        __syncthreads();
        if (kc + 2 < NC) G2_LD(kc + 2, (kc + 2) % NSTG); else CP_COMMIT();

        uint32_t sA = sb + st * STG_BYTES;
        uint32_t sB = sA + BOFF;
#pragma unroll
        for (int kk = 0; kk < 4; kk++) {
            uint32_t a[2][4];
#pragma unroll
            for (int m = 0; m < 2; m++)
                LDSM4(a[m][0], a[m][1], a[m][2], a[m][3],
                      sA + SWZ((wm + m * 16 + rA) * 128 + kk * 32 + cA));
            uint32_t b[4][4];
#pragma unroll
            for (int np = 0; np < 4; np++)
                LDSM4(b[np][0], b[np][1], b[np][2], b[np][3],
                      sB + SWZ((wn + np * 16 + rB) * 128 + kk * 32 + cB));
#pragma unroll
            for (int m = 0; m < 2; m++)
#pragma unroll
                for (int np = 0; np < 4; np++)
#pragma unroll
                    for (int j = 0; j < 2; j++)
                        mma_f16(acc[m][np * 2 + j], a[m], &b[np][j * 2]);
        }
    }

    int gid = lane >> 2, tig = lane & 3;
#pragma unroll
    for (int m = 0; m < 2; m++)
#pragma unroll
        for (int no = 0; no < 8; no++) {
            int col = n0 + wn + no * 8 + 2 * tig;
#pragma unroll
            for (int hf = 0; hf < 2; hf++) {
                int r = wm + m * 16 + gid + hf * 8;
                if (r < valid) {
                    float2 v;
                    v.x = acc[m][no][hf * 2 + 0];
                    v.y = acc[m][no][hf * 2 + 1];
                    *(float2*)(g_y + (size_t)(row0 + r) * DDIM + col) = v;
                }
            }
        }
}

// ---------------- combine + aux ----------------
__global__ void combine_kernel(float* __restrict__ out) {
    int i = blockIdx.x * blockDim.x + threadIdx.x;
    const int D4 = DDIM / 4;
    if (i >= NTOK * D4) return;
    int tok = i / D4;
    int d4 = i - tok * D4;
    int s0 = g_slot[tok * 2 + 0], s1 = g_slot[tok * 2 + 1];
    float w0 = g_wt_of_tok[tok * 2 + 0], w1 = g_wt_of_tok[tok * 2 + 1];
    const float4* y4 = (const float4*)g_y;
    float4 a = y4[(size_t)s0 * D4 + d4];
    float4 b = y4[(size_t)s1 * D4 + d4];
    float4 r;
    r.x = w0 * a.x + w1 * b.x;
    r.y = w0 * a.y + w1 * b.y;
    r.z = w0 * a.z + w1 * b.z;
    r.w = w0 * a.w + w1 * b.w;
    ((float4*)out)[i] = r;
}

__global__ void finalize_kernel(float* __restrict__ out, int out_size) {
    if (threadIdx.x != 0 || blockIdx.x != 0) return;
    if (out_size > NTOK * DDIM) {
        float s = 0.f;
        for (int e = 0; e < NEXP; e++) {
            float u = g_usage[e] / (float)NTOK;
            s += u * u;
        }
        out[NTOK * DDIM] = (float)NEXP * 0.01f * s;
    }
}

// ---------------- launch ----------------
extern "C" void kernel_launch(void* const* d_in, const int* in_sizes, int n_in,
                              void* d_out, int out_size) {
    const float* x  = (const float*)d_in[0];
    const float* rw = (const float*)d_in[1];
    const float* w1 = (const float*)d_in[2];
    const float* w2 = (const float*)d_in[3];
    const float* w3 = (const float*)d_in[4];
    float* out = (float*)d_out;

    cudaFuncSetAttribute(gemm1_mm, cudaFuncAttributeMaxDynamicSharedMemorySize, GSMEM);
    cudaFuncSetAttribute(gemm2_mm, cudaFuncAttributeMaxDynamicSharedMemorySize, GSMEM);

    __half* gxh;  cudaGetSymbolAddress((void**)&gxh,  g_xh);
    __half* gw1;  cudaGetSymbolAddress((void**)&gw1,  g_w1h);
    __half* gw3;  cudaGetSymbolAddress((void**)&gw3,  g_w3h);
    __half* gw2;  cudaGetSymbolAddress((void**)&gw2,  g_w2h);

    init_kernel<<<1, 32>>>();
    router_kernel<<<NTOK / 8, 256>>>(x, rw);
    scan_kernel<<<1, 32>>>();
    build_kernel<<<(NTOK * KTOP + 255) / 256, 256>>>();

    int nx8 = NTOK * DDIM / 8, nw8 = NEXP * HDIM * DDIM / 8;
    cvt_kernel<<<(nx8 + 255) / 256, 256>>>((const float4*)x,  (uint4*)gxh, nx8);
    cvt_kernel<<<(nw8 + 255) / 256, 256>>>((const float4*)w1, (uint4*)gw1, nw8);
    cvt_kernel<<<(nw8 + 255) / 256, 256>>>((const float4*)w3, (uint4*)gw3, nw8);
    cvt_kernel<<<(nw8 + 255) / 256, 256>>>((const float4*)w2, (uint4*)gw2, nw8);

    gemm1_mm<<<dim3(HDIM / 64, MAX_MT), 256, GSMEM>>>();
    gemm2_mm<<<dim3(DDIM / 128, MAX_MT), 256, GSMEM>>>();
    combine_kernel<<<(NTOK * (DDIM / 4) + 255) / 256, 256>>>(out);
    finalize_kernel<<<1, 32>>>(out, out_size);
}